// round 12
// baseline (speedup 1.0000x reference)
#include <cuda_runtime.h>
#include <cstdint>

#define BB 8
#define LL 512
#define CC 6
#define KK 9
#define NTOT (BB*LL)
#define BIGF 1e10f
#define POISON 5e29f
#define REAL_THR_D2 1e20f         // real d2 <= ~3e4, poisoned >= ~4e29

#define THREADS 256
#define PARTS_PER_GRAPH 64        // 8 rows per CTA, 1 row per warp
#define SCR_STRIDE 17             // u32 scratch stride per thread (odd -> conflict-free)

// dynamic smem (bytes):
//   quad planes: 6 * 512 * 16 = 49152   (plane q, node j at q*512 + j : float4)
//   scratch    : 256 * 17 * 4 = 17408
//   sec        : 512 * 4      = 2048
#define SMEM_Q_F4    (6 * LL)
#define SMEM_BYTES   (SMEM_Q_F4*16 + THREADS*SCR_STRIDE*4 + LL*4)

#define F32X2_MUL(o,a,b)   asm("mul.rn.f32x2 %0, %1, %2;"     : "=l"(o) : "l"(a), "l"(b))
#define F32X2_ADD(o,a,b)   asm("add.rn.f32x2 %0, %1, %2;"     : "=l"(o) : "l"(a), "l"(b))
#define F32X2_FMA(o,a,b,c) asm("fma.rn.f32x2 %0, %1, %2, %3;" : "=l"(o) : "l"(a), "l"(b), "l"(c))
#define PACK2(o,f)         asm("mov.b64 %0, {%1, %1};"        : "=l"(o) : "r"(__float_as_uint(f)))
#define UNPACK2(lo,hi,v)   asm("mov.b64 {%0, %1}, %2;"        : "=r"(lo), "=r"(hi) : "l"(v))

// compare-exchange on packed (d2bits<<9 | idx) u64s — lexicographic (key, idx)
#define CE(a,b) { unsigned long long _x=v[a], _y=v[b]; bool _p=_x<_y; v[a]=_p?_x:_y; v[b]=_p?_y:_x; }

// Output layout (float32, reference return order):
//   [0) dknn 36864 | [36864) src | [73728) dst | [110592) valid | [147456) glb 16368 | [163824) seq 16320

extern "C" __global__ void __launch_bounds__(THREADS, 3)
knn_kernel(const float* __restrict__ X, const int* __restrict__ AP,
           const int* __restrict__ S, const int* __restrict__ sec,
           float* __restrict__ out)
{
    extern __shared__ float4 sQ[];                    // 6 planes of 512 float4
    unsigned* sScr = (unsigned*)(sQ + SMEM_Q_F4);
    int*      sSec = (int*)(sScr + THREADS*SCR_STRIDE);

    const int g     = blockIdx.x / PARTS_PER_GRAPH;
    const int part  = blockIdx.x % PARTS_PER_GRAPH;
    const int gbase = g * LL;
    const int tid   = threadIdx.x;

    // ---- structural edges (independent of smem; folded in) ----
    {
        const int GLB_PER = 2*LL - 1, SEQ_PER = 2*(LL - 2);
        const int NG = BB*GLB_PER, NS = BB*SEQ_PER;
        float* gq = out + 4*(size_t)NTOT*KK;
        float* sq = gq + 2*NG;
        int t = blockIdx.x * THREADS + tid;
        if (t < NG) {
            int b = t / GLB_PER, e = t % GLB_PER;
            int srcl = (e < LL) ? 0 : (e - LL + 1);
            int dstl = (e < LL) ? e : 0;
            gq[t]      = (float)(srcl + b*LL);
            gq[NG + t] = (float)(dstl + b*LL);
        } else if (t < NG + NS) {
            int u = t - NG;
            int b = u / SEQ_PER, e = u % SEQ_PER;
            int half = LL - 2;
            int srcl = (e < half) ? (1 + e) : (2 + (e - half));
            int dstl = (e < half) ? (2 + e) : (1 + (e - half));
            sq[u]      = (float)(srcl + b*LL);
            sq[NS + u] = (float)(dstl + b*LL);
        }
    }

    // ---- stage graph table, SoA quad planes, channel-paired for f32x2 ----
    for (int j = tid; j < LL; j += THREADS) {
        const float* xp  = X  + (size_t)(gbase + j) * (CC*3);
        const int*   app = AP + (size_t)(gbase + j) * CC;
        bool bos = (S[gbase + j] == 0);
        float xs[CC], ys[CC], zs[CC], ws[CC];
        #pragma unroll
        for (int c = 0; c < CC; ++c) {
            float x = xp[c*3+0], y = xp[c*3+1], z = xp[c*3+2];
            float sq = x*x + y*y + z*z;               // identical to passing kernel
            if (bos || app[c] == 0) sq = POISON;
            xs[c] = x; ys[c] = y; zs[c] = z; ws[c] = sq;
        }
        #pragma unroll
        for (int dp = 0; dp < 3; ++dp) {
            int c0 = 2*dp, c1 = 2*dp + 1;
            sQ[(2*dp + 0)*LL + j] = make_float4(xs[c0], xs[c1], ys[c0], ys[c1]);
            sQ[(2*dp + 1)*LL + j] = make_float4(zs[c0], zs[c1], ws[c0], ws[c1]);
        }
        sSec[j] = sec[gbase + j];
    }
    __syncthreads();

    const int warp = tid >> 5, lane = tid & 31;
    const int il   = part * 8 + warp;                 // this warp's row (1 row/warp)
    const int ig   = gbase + il;

    unsigned long long neg2; PACK2(neg2, -2.0f);

    // row-constant broadcast pairs
    unsigned long long bx0[CC], bx1[CC], bx2[CC], bsq[CC];
    #pragma unroll
    for (int dp = 0; dp < 3; ++dp) {
        float4 a = sQ[(2*dp + 0)*LL + il];
        float4 b = sQ[(2*dp + 1)*LL + il];
        int c0 = 2*dp, c1 = 2*dp + 1;
        PACK2(bx0[c0], a.x); PACK2(bx0[c1], a.y);
        PACK2(bx1[c0], a.z); PACK2(bx1[c1], a.w);
        PACK2(bx2[c0], b.x); PACK2(bx2[c1], b.y);
        PACK2(bsq[c0], b.z); PACK2(bsq[c1], b.w);
    }

    unsigned* scr = sScr + tid * SCR_STRIDE;

    // ---- distance loop: 1 STS per candidate, no selection in loop ----
    #pragma unroll 2
    for (int jt = 0; jt < 16; ++jt) {
        const int j = (jt << 5) | lane;
        const ulonglong2* q0 = (const ulonglong2*)&sQ[0*LL + j];
        const ulonglong2* q1 = (const ulonglong2*)&sQ[1*LL + j];
        const ulonglong2* q2 = (const ulonglong2*)&sQ[2*LL + j];
        const ulonglong2* q3 = (const ulonglong2*)&sQ[3*LL + j];
        const ulonglong2* q4 = (const ulonglong2*)&sQ[4*LL + j];
        const ulonglong2* q5 = (const ulonglong2*)&sQ[5*LL + j];
        ulonglong2 p0 = *q0, p1 = *q1, p2 = *q2, p3 = *q3, p4 = *q4, p5 = *q5;

        float m = 3.4e38f;
        #pragma unroll
        for (int c = 0; c < CC; ++c) {
            unsigned long long t0, t1, t2, s0, s1, s2, e0, e1, e2;
            F32X2_MUL(t0, bx2[c], p1.x); F32X2_FMA(t0, bx1[c], p0.y, t0); F32X2_FMA(t0, bx0[c], p0.x, t0);
            F32X2_MUL(t1, bx2[c], p3.x); F32X2_FMA(t1, bx1[c], p2.y, t1); F32X2_FMA(t1, bx0[c], p2.x, t1);
            F32X2_MUL(t2, bx2[c], p5.x); F32X2_FMA(t2, bx1[c], p4.y, t2); F32X2_FMA(t2, bx0[c], p4.x, t2);
            F32X2_ADD(s0, bsq[c], p1.y); F32X2_FMA(e0, neg2, t0, s0);
            F32X2_ADD(s1, bsq[c], p3.y); F32X2_FMA(e1, neg2, t1, s1);
            F32X2_ADD(s2, bsq[c], p5.y); F32X2_FMA(e2, neg2, t2, s2);
            unsigned l0, h0, l1, h1, l2, h2;
            UNPACK2(l0, h0, e0); UNPACK2(l1, h1, e1); UNPACK2(l2, h2, e2);
            float m01 = fminf(__uint_as_float(l0), __uint_as_float(h0));
            float m23 = fminf(__uint_as_float(l1), __uint_as_float(h1));
            float m45 = fminf(__uint_as_float(l2), __uint_as_float(h2));
            m = fminf(m, fminf(fminf(m01, m23), m45));
        }
        m = fmaxf(m, 0.0f);                           // reference's per-pair clamp
        scr[jt] = __float_as_uint(m);                 // nonneg float: uint order == float order
    }

    // ---- per-lane selection: load 16 keys, pack (key<<9|j), Batcher sort-16 ----
    unsigned long long v[16];
    #pragma unroll
    for (int t = 0; t < 16; ++t) {
        unsigned kk = scr[t];
        v[t] = (((unsigned long long)kk) << 9) | (unsigned)((t << 5) | lane);
    }
    // Batcher odd-even mergesort, 16 inputs, 63 CEs
    CE(0,1) CE(2,3) CE(4,5) CE(6,7) CE(8,9) CE(10,11) CE(12,13) CE(14,15)
    CE(0,2) CE(1,3) CE(4,6) CE(5,7) CE(8,10) CE(9,11) CE(12,14) CE(13,15)
    CE(1,2) CE(5,6) CE(9,10) CE(13,14)
    CE(0,4) CE(1,5) CE(2,6) CE(3,7) CE(8,12) CE(9,13) CE(10,14) CE(11,15)
    CE(2,4) CE(3,5) CE(10,12) CE(11,13)
    CE(1,2) CE(3,4) CE(5,6) CE(9,10) CE(11,12) CE(13,14)
    CE(0,8) CE(1,9) CE(2,10) CE(3,11) CE(4,12) CE(5,13) CE(6,14) CE(7,15)
    CE(4,8) CE(5,9) CE(6,10) CE(7,11)
    CE(2,4) CE(3,5) CE(6,8) CE(7,9) CE(10,12) CE(11,13)
    CE(1,2) CE(3,4) CE(5,6) CE(7,8) CE(9,10) CE(11,12) CE(13,14)

    // ---- warp merge via redux: 9 rounds, lexicographic (key, idx) min ----
    const int seci = sSec[il];
    #pragma unroll 1
    for (int r = 0; r < KK; ++r) {
        unsigned mykey = (unsigned)(v[0] >> 9);
        unsigned kmin  = __reduce_min_sync(0xffffffffu, mykey);
        unsigned myidx = (unsigned)v[0] & 511u;
        unsigned cand  = (mykey == kmin) ? myidx : 1023u;
        unsigned imin  = __reduce_min_sync(0xffffffffu, cand);
        if (mykey == kmin && myidx == imin) {         // exactly one winner
            float d2v  = __uint_as_float(kmin);
            bool  real = (d2v < REAL_THR_D2);
            float dv   = real ? sqrtf(d2v) : BIGF;
            bool  valid = real && (seci == sSec[imin]);
            size_t o0 = (size_t)ig * KK + r;
            out[o0]                        = dv;
            out[(size_t)NTOT*KK     + o0]  = (float)ig;
            out[2*(size_t)NTOT*KK   + o0]  = valid ? (float)(gbase + (int)imin) : -1.0f;
            out[3*(size_t)NTOT*KK   + o0]  = valid ? 1.0f : 0.0f;
            #pragma unroll
            for (int t = 0; t < 8; ++t) v[t] = v[t+1];   // pop head (winner only)
        }
    }
}

extern "C" void kernel_launch(void* const* d_in, const int* in_sizes, int n_in,
                              void* d_out, int out_size)
{
    const float* X   = (const float*)d_in[0];
    const int*   AP  = (const int*)d_in[1];
    const int*   S   = (const int*)d_in[2];
    const int*   sec = (const int*)d_in[3];
    float* out = (float*)d_out;

    cudaFuncSetAttribute((const void*)knn_kernel,
                         cudaFuncAttributeMaxDynamicSharedMemorySize, SMEM_BYTES);
    knn_kernel<<<BB * PARTS_PER_GRAPH, THREADS, SMEM_BYTES>>>(X, AP, S, sec, out);
}

// round 14
// speedup vs baseline: 1.1811x; 1.1811x over previous
#include <cuda_runtime.h>
#include <cstdint>

#define BB 8
#define LL 512
#define CC 6
#define KK 9
#define NTOT (BB*LL)
#define BIGF 1e10f
#define POISON 5e29f
#define REAL_THR_D2 1e20f         // real d2 <= ~3e4, poisoned >= ~4e29

#define NBANDS 16                 // 16 bands of 32 rows per graph
#define NPAIRS 136                // NBANDS*(NBANDS+1)/2

__device__ unsigned g_keys[(size_t)NTOT * LL];   // 8 MB key scratch (static: no allocs)

#define F32X2_MUL(o,a,b)   asm("mul.rn.f32x2 %0, %1, %2;"     : "=l"(o) : "l"(a), "l"(b))
#define F32X2_ADD(o,a,b)   asm("add.rn.f32x2 %0, %1, %2;"     : "=l"(o) : "l"(a), "l"(b))
#define F32X2_FMA(o,a,b,c) asm("fma.rn.f32x2 %0, %1, %2, %3;" : "=l"(o) : "l"(a), "l"(b), "l"(c))
#define UNPACK2(lo,hi,v)   asm("mov.b64 {%0, %1}, %2;"        : "=r"(lo), "=r"(hi) : "l"(v))

static __device__ __forceinline__ unsigned long long dup_f(float f) {
    unsigned b = __float_as_uint(f);
    return (unsigned long long)b | ((unsigned long long)b << 32);
}
static __device__ __forceinline__ unsigned long long pack_f(float a, float b) {
    return (unsigned long long)__float_as_uint(a)
         | ((unsigned long long)__float_as_uint(b) << 32);
}

// one broadcast-channel block: 3 packed chains over data pairs p0..p5.
// EXACT arithmetic of the validated kernel: dot chain, s = sqi+sqj, e = fma(-2,dot,s).
#define CHAN(BX0,BX1,BX2,BSQ)                                                          \
{                                                                                      \
    unsigned long long t0,t1,t2,s0,s1,s2,e0,e1,e2;                                     \
    F32X2_MUL(t0, BX2, p1.x); F32X2_FMA(t0, BX1, p0.y, t0); F32X2_FMA(t0, BX0, p0.x, t0); \
    F32X2_MUL(t1, BX2, p3.x); F32X2_FMA(t1, BX1, p2.y, t1); F32X2_FMA(t1, BX0, p2.x, t1); \
    F32X2_MUL(t2, BX2, p5.x); F32X2_FMA(t2, BX1, p4.y, t2); F32X2_FMA(t2, BX0, p4.x, t2); \
    F32X2_ADD(s0, BSQ, p1.y); F32X2_FMA(e0, neg2, t0, s0);                             \
    F32X2_ADD(s1, BSQ, p3.y); F32X2_FMA(e1, neg2, t1, s1);                             \
    F32X2_ADD(s2, BSQ, p5.y); F32X2_FMA(e2, neg2, t2, s2);                             \
    unsigned l0,h0,l1,h1,l2,h2;                                                        \
    UNPACK2(l0,h0,e0); UNPACK2(l1,h1,e1); UNPACK2(l2,h2,e2);                           \
    float m01 = fminf(__uint_as_float(l0), __uint_as_float(h0));                       \
    float m23 = fminf(__uint_as_float(l1), __uint_as_float(h1));                       \
    float m45 = fminf(__uint_as_float(l2), __uint_as_float(h2));                       \
    m = fminf(m, fminf(fminf(m01, m23), m45));                                         \
}

// ---------------- Phase 1: symmetric distance tiles ----------------
extern "C" __global__ void __launch_bounds__(128)
dist_kernel(const float* __restrict__ X, const int* __restrict__ AP,
            const int* __restrict__ S)
{
    __shared__ ulonglong2 sI[32][12];      // band-I broadcast table, pre-duplicated pairs

    const int g = blockIdx.x / NPAIRS;
    int p = blockIdx.x % NPAIRS;
    int I = 0, cnt = NBANDS;
    while (p >= cnt) { p -= cnt; ++I; --cnt; }
    const int J = I + p;
    const int gbase = g * LL;
    const int tid = threadIdx.x, warp = tid >> 5, lane = tid & 31;

    // stage band I (32 nodes) as dup-packed broadcast operands
    if (tid < 32) {
        int node = gbase + I*32 + tid;
        const float* xp  = X  + (size_t)node * (CC*3);
        const int*   app = AP + (size_t)node * CC;
        bool bos = (S[node] == 0);
        #pragma unroll
        for (int dp = 0; dp < 3; ++dp) {
            int c0 = 2*dp, c1 = c0 + 1;
            float x0 = xp[c0*3], y0 = xp[c0*3+1], z0 = xp[c0*3+2];
            float x1 = xp[c1*3], y1 = xp[c1*3+1], z1 = xp[c1*3+2];
            float s0 = x0*x0 + y0*y0 + z0*z0;            // identical expression to validated kernel
            float s1 = x1*x1 + y1*y1 + z1*z1;
            if (bos || app[c0] == 0) s0 = POISON;
            if (bos || app[c1] == 0) s1 = POISON;
            sI[tid][dp*4+0] = make_ulonglong2(dup_f(x0), dup_f(x1));
            sI[tid][dp*4+1] = make_ulonglong2(dup_f(y0), dup_f(y1));
            sI[tid][dp*4+2] = make_ulonglong2(dup_f(z0), dup_f(z1));
            sI[tid][dp*4+3] = make_ulonglong2(dup_f(s0), dup_f(s1));
        }
    }

    // lane-resident band-J node data (pair-packed, validated layout)
    ulonglong2 p0, p1, p2, p3, p4, p5;
    {
        int node = gbase + J*32 + lane;
        const float* xp  = X  + (size_t)node * (CC*3);
        const int*   app = AP + (size_t)node * CC;
        bool bos = (S[node] == 0);
        float xs[CC], ys[CC], zs[CC], ws[CC];
        #pragma unroll
        for (int c = 0; c < CC; ++c) {
            float x = xp[c*3], y = xp[c*3+1], z = xp[c*3+2];
            float sq = x*x + y*y + z*z;
            if (bos || app[c] == 0) sq = POISON;
            xs[c] = x; ys[c] = y; zs[c] = z; ws[c] = sq;
        }
        p0 = make_ulonglong2(pack_f(xs[0], xs[1]), pack_f(ys[0], ys[1]));
        p1 = make_ulonglong2(pack_f(zs[0], zs[1]), pack_f(ws[0], ws[1]));
        p2 = make_ulonglong2(pack_f(xs[2], xs[3]), pack_f(ys[2], ys[3]));
        p3 = make_ulonglong2(pack_f(zs[2], zs[3]), pack_f(ws[2], ws[3]));
        p4 = make_ulonglong2(pack_f(xs[4], xs[5]), pack_f(ys[4], ys[5]));
        p5 = make_ulonglong2(pack_f(zs[4], zs[5]), pack_f(ws[4], ws[5]));
    }
    __syncthreads();

    const unsigned long long neg2 = dup_f(-2.0f);

    unsigned tk[8];
    #pragma unroll 2
    for (int s = 0; s < 8; ++s) {
        const int ii = warp*8 + s;                       // i within band I
        const ulonglong2* bq = sI[ii];
        ulonglong2 b0 = bq[0], b1 = bq[1], b2  = bq[2],  b3  = bq[3],
                   b4 = bq[4], b5 = bq[5], b6  = bq[6],  b7  = bq[7],
                   b8 = bq[8], b9 = bq[9], b10 = bq[10], b11 = bq[11];
        float m = 3.4e38f;
        CHAN(b0.x, b1.x, b2.x,  b3.x)     // channel 0
        CHAN(b0.y, b1.y, b2.y,  b3.y)     // channel 1
        CHAN(b4.x, b5.x, b6.x,  b7.x)     // channel 2
        CHAN(b4.y, b5.y, b6.y,  b7.y)     // channel 3
        CHAN(b8.x, b9.x, b10.x, b11.x)    // channel 4
        CHAN(b8.y, b9.y, b10.y, b11.y)    // channel 5
        m = fmaxf(m, 0.0f);               // reference's per-pair clamp (exact: clamp(min)==min(clamp))
        unsigned key = __float_as_uint(m);
        g_keys[(size_t)(gbase + I*32 + ii)*LL + J*32 + lane] = key;   // row side (coalesced)
        tk[s] = key;
    }
    if (I != J) {                         // column side: row (J*32+lane), cols I*32+warp*8..+7
        unsigned* dst = &g_keys[(size_t)(gbase + J*32 + lane)*LL + I*32 + warp*8];
        *(uint4*)(dst)     = make_uint4(tk[0], tk[1], tk[2], tk[3]);
        *(uint4*)(dst + 4) = make_uint4(tk[4], tk[5], tk[6], tk[7]);
    }
}

// ---------------- Phase 2: per-row top-9 + outputs + edges ----------------
#define CE(a,b) { unsigned long long _x=v[a], _y=v[b]; bool _p=_x<_y; v[a]=_p?_x:_y; v[b]=_p?_y:_x; }

extern "C" __global__ void __launch_bounds__(256)
topk_kernel(const int* __restrict__ sec, float* __restrict__ out)
{
    __shared__ int sSec[LL];

    const int g     = blockIdx.x / 64;               // 64 CTAs per graph, 8 rows each
    const int part  = blockIdx.x % 64;
    const int gbase = g * LL;
    const int tid   = threadIdx.x;

    // structural edges (grid*256 = 131072 threads cover 16344 slots)
    {
        const int GLB_PER = 2*LL - 1, SEQ_PER = 2*(LL - 2);
        const int NG = BB*GLB_PER, NS = BB*SEQ_PER;
        float* gq = out + 4*(size_t)NTOT*KK;
        float* sq = gq + 2*NG;
        int t = blockIdx.x * 256 + tid;
        if (t < NG) {
            int b = t / GLB_PER, e = t % GLB_PER;
            int srcl = (e < LL) ? 0 : (e - LL + 1);
            int dstl = (e < LL) ? e : 0;
            gq[t]      = (float)(srcl + b*LL);
            gq[NG + t] = (float)(dstl + b*LL);
        } else if (t < NG + NS) {
            int u = t - NG;
            int b = u / SEQ_PER, e = u % SEQ_PER;
            int half = LL - 2;
            int srcl = (e < half) ? (1 + e) : (2 + (e - half));
            int dstl = (e < half) ? (2 + e) : (1 + (e - half));
            sq[u]      = (float)(srcl + b*LL);
            sq[NS + u] = (float)(dstl + b*LL);
        }
    }

    sSec[tid]       = sec[gbase + tid];
    sSec[tid + 256] = sec[gbase + tid + 256];
    __syncthreads();

    const int warp = tid >> 5, lane = tid & 31;
    const int il   = part * 8 + warp;                // this warp's row
    const int ig   = gbase + il;

    // load this row's 512 keys: lane owns j = lane*16 .. lane*16+15
    const unsigned* row = &g_keys[(size_t)ig * LL + lane*16];
    uint4 k0 = *(const uint4*)(row + 0);
    uint4 k1 = *(const uint4*)(row + 4);
    uint4 k2 = *(const uint4*)(row + 8);
    uint4 k3 = *(const uint4*)(row + 12);

    unsigned long long v[16];
    {
        unsigned base = (unsigned)(lane*16);
        v[0]=(((unsigned long long)k0.x)<<9)|(base+0);  v[1]=(((unsigned long long)k0.y)<<9)|(base+1);
        v[2]=(((unsigned long long)k0.z)<<9)|(base+2);  v[3]=(((unsigned long long)k0.w)<<9)|(base+3);
        v[4]=(((unsigned long long)k1.x)<<9)|(base+4);  v[5]=(((unsigned long long)k1.y)<<9)|(base+5);
        v[6]=(((unsigned long long)k1.z)<<9)|(base+6);  v[7]=(((unsigned long long)k1.w)<<9)|(base+7);
        v[8]=(((unsigned long long)k2.x)<<9)|(base+8);  v[9]=(((unsigned long long)k2.y)<<9)|(base+9);
        v[10]=(((unsigned long long)k2.z)<<9)|(base+10); v[11]=(((unsigned long long)k2.w)<<9)|(base+11);
        v[12]=(((unsigned long long)k3.x)<<9)|(base+12); v[13]=(((unsigned long long)k3.y)<<9)|(base+13);
        v[14]=(((unsigned long long)k3.z)<<9)|(base+14); v[15]=(((unsigned long long)k3.w)<<9)|(base+15);
    }
    // Batcher odd-even mergesort, 16 inputs, 63 CEs
    CE(0,1) CE(2,3) CE(4,5) CE(6,7) CE(8,9) CE(10,11) CE(12,13) CE(14,15)
    CE(0,2) CE(1,3) CE(4,6) CE(5,7) CE(8,10) CE(9,11) CE(12,14) CE(13,15)
    CE(1,2) CE(5,6) CE(9,10) CE(13,14)
    CE(0,4) CE(1,5) CE(2,6) CE(3,7) CE(8,12) CE(9,13) CE(10,14) CE(11,15)
    CE(2,4) CE(3,5) CE(10,12) CE(11,13)
    CE(1,2) CE(3,4) CE(5,6) CE(9,10) CE(11,12) CE(13,14)
    CE(0,8) CE(1,9) CE(2,10) CE(3,11) CE(4,12) CE(5,13) CE(6,14) CE(7,15)
    CE(4,8) CE(5,9) CE(6,10) CE(7,11)
    CE(2,4) CE(3,5) CE(6,8) CE(7,9) CE(10,12) CE(11,13)
    CE(1,2) CE(3,4) CE(5,6) CE(7,8) CE(9,10) CE(11,12) CE(13,14)

    // warp merge via redux: 9 rounds, lexicographic (key, idx) min
    const int seci = sSec[il];
    #pragma unroll 1
    for (int r = 0; r < KK; ++r) {
        unsigned mykey = (unsigned)(v[0] >> 9);
        unsigned kmin  = __reduce_min_sync(0xffffffffu, mykey);
        unsigned myidx = (unsigned)v[0] & 511u;
        unsigned cand  = (mykey == kmin) ? myidx : 1023u;
        unsigned imin  = __reduce_min_sync(0xffffffffu, cand);
        if (mykey == kmin && myidx == imin) {        // exactly one winner
            float d2v  = __uint_as_float(kmin);
            bool  real = (d2v < REAL_THR_D2);
            float dv   = real ? sqrtf(d2v) : BIGF;
            bool  valid = real && (seci == sSec[imin]);
            size_t o0 = (size_t)ig * KK + r;
            out[o0]                        = dv;
            out[(size_t)NTOT*KK     + o0]  = (float)ig;
            out[2*(size_t)NTOT*KK   + o0]  = valid ? (float)(gbase + (int)imin) : -1.0f;
            out[3*(size_t)NTOT*KK   + o0]  = valid ? 1.0f : 0.0f;
            #pragma unroll
            for (int t = 0; t < 8; ++t) v[t] = v[t+1];   // pop head (winner only)
        }
    }
}

extern "C" void kernel_launch(void* const* d_in, const int* in_sizes, int n_in,
                              void* d_out, int out_size)
{
    const float* X   = (const float*)d_in[0];
    const int*   AP  = (const int*)d_in[1];
    const int*   S   = (const int*)d_in[2];
    const int*   sec = (const int*)d_in[3];
    float* out = (float*)d_out;

    dist_kernel<<<BB * NPAIRS, 128>>>(X, AP, S);        // 1088 CTAs
    topk_kernel<<<BB * 64, 256>>>(sec, out);            // 512 CTAs
}

// round 15
// speedup vs baseline: 1.2582x; 1.0652x over previous
#include <cuda_runtime.h>
#include <cstdint>

#define BB 8
#define LL 512
#define CC 6
#define KK 9
#define NTOT (BB*LL)
#define BIGF 1e10f
#define POISON 5e29f
#define REAL_THR_D2 1e20f         // real d2 <= ~3e4, poisoned >= ~4e29

#define NBANDS 16                 // 16 bands of 32 rows per graph
#define NPAIRS 136                // NBANDS*(NBANDS+1)/2

__device__ unsigned g_keys[(size_t)NTOT * LL];   // 8 MB key scratch (static: no allocs)

#define F32X2_MUL(o,a,b)   asm("mul.rn.f32x2 %0, %1, %2;"     : "=l"(o) : "l"(a), "l"(b))
#define F32X2_ADD(o,a,b)   asm("add.rn.f32x2 %0, %1, %2;"     : "=l"(o) : "l"(a), "l"(b))
#define F32X2_FMA(o,a,b,c) asm("fma.rn.f32x2 %0, %1, %2, %3;" : "=l"(o) : "l"(a), "l"(b), "l"(c))
#define UNPACK2(lo,hi,v)   asm("mov.b64 {%0, %1}, %2;"        : "=r"(lo), "=r"(hi) : "l"(v))

static __device__ __forceinline__ unsigned long long dup_f(float f) {
    unsigned b = __float_as_uint(f);
    return (unsigned long long)b | ((unsigned long long)b << 32);
}
static __device__ __forceinline__ unsigned long long pack_f(float a, float b) {
    return (unsigned long long)__float_as_uint(a)
         | ((unsigned long long)__float_as_uint(b) << 32);
}

// one broadcast-channel block: 3 packed chains over data pairs p0..p5.
// EXACT arithmetic of the validated kernel: dot chain, s = sqi+sqj, e = fma(-2,dot,s).
#define CHAN(BX0,BX1,BX2,BSQ)                                                          \
{                                                                                      \
    unsigned long long t0,t1,t2,s0,s1,s2,e0,e1,e2;                                     \
    F32X2_MUL(t0, BX2, p1.x); F32X2_FMA(t0, BX1, p0.y, t0); F32X2_FMA(t0, BX0, p0.x, t0); \
    F32X2_MUL(t1, BX2, p3.x); F32X2_FMA(t1, BX1, p2.y, t1); F32X2_FMA(t1, BX0, p2.x, t1); \
    F32X2_MUL(t2, BX2, p5.x); F32X2_FMA(t2, BX1, p4.y, t2); F32X2_FMA(t2, BX0, p4.x, t2); \
    F32X2_ADD(s0, BSQ, p1.y); F32X2_FMA(e0, neg2, t0, s0);                             \
    F32X2_ADD(s1, BSQ, p3.y); F32X2_FMA(e1, neg2, t1, s1);                             \
    F32X2_ADD(s2, BSQ, p5.y); F32X2_FMA(e2, neg2, t2, s2);                             \
    unsigned l0,h0,l1,h1,l2,h2;                                                        \
    UNPACK2(l0,h0,e0); UNPACK2(l1,h1,e1); UNPACK2(l2,h2,e2);                           \
    float m01 = fminf(__uint_as_float(l0), __uint_as_float(h0));                       \
    float m23 = fminf(__uint_as_float(l1), __uint_as_float(h1));                       \
    float m45 = fminf(__uint_as_float(l2), __uint_as_float(h2));                       \
    m = fminf(m, fminf(fminf(m01, m23), m45));                                         \
}

// ---------------- Phase 1: symmetric distance tiles (UNCHANGED, validated) ----------------
extern "C" __global__ void __launch_bounds__(128)
dist_kernel(const float* __restrict__ X, const int* __restrict__ AP,
            const int* __restrict__ S)
{
    __shared__ ulonglong2 sI[32][12];      // band-I broadcast table, pre-duplicated pairs

    const int g = blockIdx.x / NPAIRS;
    int p = blockIdx.x % NPAIRS;
    int I = 0, cnt = NBANDS;
    while (p >= cnt) { p -= cnt; ++I; --cnt; }
    const int J = I + p;
    const int gbase = g * LL;
    const int tid = threadIdx.x, warp = tid >> 5, lane = tid & 31;

    if (tid < 32) {
        int node = gbase + I*32 + tid;
        const float* xp  = X  + (size_t)node * (CC*3);
        const int*   app = AP + (size_t)node * CC;
        bool bos = (S[node] == 0);
        #pragma unroll
        for (int dp = 0; dp < 3; ++dp) {
            int c0 = 2*dp, c1 = c0 + 1;
            float x0 = xp[c0*3], y0 = xp[c0*3+1], z0 = xp[c0*3+2];
            float x1 = xp[c1*3], y1 = xp[c1*3+1], z1 = xp[c1*3+2];
            float s0 = x0*x0 + y0*y0 + z0*z0;
            float s1 = x1*x1 + y1*y1 + z1*z1;
            if (bos || app[c0] == 0) s0 = POISON;
            if (bos || app[c1] == 0) s1 = POISON;
            sI[tid][dp*4+0] = make_ulonglong2(dup_f(x0), dup_f(x1));
            sI[tid][dp*4+1] = make_ulonglong2(dup_f(y0), dup_f(y1));
            sI[tid][dp*4+2] = make_ulonglong2(dup_f(z0), dup_f(z1));
            sI[tid][dp*4+3] = make_ulonglong2(dup_f(s0), dup_f(s1));
        }
    }

    ulonglong2 p0, p1, p2, p3, p4, p5;
    {
        int node = gbase + J*32 + lane;
        const float* xp  = X  + (size_t)node * (CC*3);
        const int*   app = AP + (size_t)node * CC;
        bool bos = (S[node] == 0);
        float xs[CC], ys[CC], zs[CC], ws[CC];
        #pragma unroll
        for (int c = 0; c < CC; ++c) {
            float x = xp[c*3], y = xp[c*3+1], z = xp[c*3+2];
            float sq = x*x + y*y + z*z;
            if (bos || app[c] == 0) sq = POISON;
            xs[c] = x; ys[c] = y; zs[c] = z; ws[c] = sq;
        }
        p0 = make_ulonglong2(pack_f(xs[0], xs[1]), pack_f(ys[0], ys[1]));
        p1 = make_ulonglong2(pack_f(zs[0], zs[1]), pack_f(ws[0], ws[1]));
        p2 = make_ulonglong2(pack_f(xs[2], xs[3]), pack_f(ys[2], ys[3]));
        p3 = make_ulonglong2(pack_f(zs[2], zs[3]), pack_f(ws[2], ws[3]));
        p4 = make_ulonglong2(pack_f(xs[4], xs[5]), pack_f(ys[4], ys[5]));
        p5 = make_ulonglong2(pack_f(zs[4], zs[5]), pack_f(ws[4], ws[5]));
    }
    __syncthreads();

    const unsigned long long neg2 = dup_f(-2.0f);

    unsigned tk[8];
    #pragma unroll 2
    for (int s = 0; s < 8; ++s) {
        const int ii = warp*8 + s;
        const ulonglong2* bq = sI[ii];
        ulonglong2 b0 = bq[0], b1 = bq[1], b2  = bq[2],  b3  = bq[3],
                   b4 = bq[4], b5 = bq[5], b6  = bq[6],  b7  = bq[7],
                   b8 = bq[8], b9 = bq[9], b10 = bq[10], b11 = bq[11];
        float m = 3.4e38f;
        CHAN(b0.x, b1.x, b2.x,  b3.x)
        CHAN(b0.y, b1.y, b2.y,  b3.y)
        CHAN(b4.x, b5.x, b6.x,  b7.x)
        CHAN(b4.y, b5.y, b6.y,  b7.y)
        CHAN(b8.x, b9.x, b10.x, b11.x)
        CHAN(b8.y, b9.y, b10.y, b11.y)
        m = fmaxf(m, 0.0f);
        unsigned key = __float_as_uint(m);
        g_keys[(size_t)(gbase + I*32 + ii)*LL + J*32 + lane] = key;
        tk[s] = key;
    }
    if (I != J) {
        unsigned* dst = &g_keys[(size_t)(gbase + J*32 + lane)*LL + I*32 + warp*8];
        *(uint4*)(dst)     = make_uint4(tk[0], tk[1], tk[2], tk[3]);
        *(uint4*)(dst + 4) = make_uint4(tk[4], tk[5], tk[6], tk[7]);
    }
}

// ---------------- Phase 2: per-row top-9 + outputs + edges ----------------
#define CE(a,b) { unsigned long long _x=v[a], _y=v[b]; bool _p=_x<_y; v[a]=_p?_x:_y; v[b]=_p?_y:_x; }

extern "C" __global__ void __launch_bounds__(256)
topk_kernel(const int* __restrict__ sec, float* __restrict__ out)
{
    __shared__ int sSec[LL];

    const int g     = blockIdx.x / 64;               // 64 CTAs per graph, 8 rows each
    const int part  = blockIdx.x % 64;
    const int gbase = g * LL;
    const int tid   = threadIdx.x;

    // structural edges
    {
        const int GLB_PER = 2*LL - 1, SEQ_PER = 2*(LL - 2);
        const int NG = BB*GLB_PER, NS = BB*SEQ_PER;
        float* gq = out + 4*(size_t)NTOT*KK;
        float* sq = gq + 2*NG;
        int t = blockIdx.x * 256 + tid;
        if (t < NG) {
            int b = t / GLB_PER, e = t % GLB_PER;
            int srcl = (e < LL) ? 0 : (e - LL + 1);
            int dstl = (e < LL) ? e : 0;
            gq[t]      = (float)(srcl + b*LL);
            gq[NG + t] = (float)(dstl + b*LL);
        } else if (t < NG + NS) {
            int u = t - NG;
            int b = u / SEQ_PER, e = u % SEQ_PER;
            int half = LL - 2;
            int srcl = (e < half) ? (1 + e) : (2 + (e - half));
            int dstl = (e < half) ? (2 + e) : (1 + (e - half));
            sq[u]      = (float)(srcl + b*LL);
            sq[NS + u] = (float)(dstl + b*LL);
        }
    }

    sSec[tid]       = sec[gbase + tid];
    sSec[tid + 256] = sec[gbase + tid + 256];
    __syncthreads();

    const int warp = tid >> 5, lane = tid & 31;
    const int il   = part * 8 + warp;                // this warp's row
    const int ig   = gbase + il;

    // load this row's 512 keys: lane owns j = lane*16 .. lane*16+15
    const unsigned* row = &g_keys[(size_t)ig * LL + lane*16];
    uint4 k0 = *(const uint4*)(row + 0);
    uint4 k1 = *(const uint4*)(row + 4);
    uint4 k2 = *(const uint4*)(row + 8);
    uint4 k3 = *(const uint4*)(row + 12);

    unsigned long long v[16];
    {
        unsigned base = (unsigned)(lane*16);
        v[0]=(((unsigned long long)k0.x)<<9)|(base+0);  v[1]=(((unsigned long long)k0.y)<<9)|(base+1);
        v[2]=(((unsigned long long)k0.z)<<9)|(base+2);  v[3]=(((unsigned long long)k0.w)<<9)|(base+3);
        v[4]=(((unsigned long long)k1.x)<<9)|(base+4);  v[5]=(((unsigned long long)k1.y)<<9)|(base+5);
        v[6]=(((unsigned long long)k1.z)<<9)|(base+6);  v[7]=(((unsigned long long)k1.w)<<9)|(base+7);
        v[8]=(((unsigned long long)k2.x)<<9)|(base+8);  v[9]=(((unsigned long long)k2.y)<<9)|(base+9);
        v[10]=(((unsigned long long)k2.z)<<9)|(base+10); v[11]=(((unsigned long long)k2.w)<<9)|(base+11);
        v[12]=(((unsigned long long)k3.x)<<9)|(base+12); v[13]=(((unsigned long long)k3.y)<<9)|(base+13);
        v[14]=(((unsigned long long)k3.z)<<9)|(base+14); v[15]=(((unsigned long long)k3.w)<<9)|(base+15);
    }
    // Batcher odd-even mergesort, pruned to outputs 0..8 (58 CEs)
    CE(0,1) CE(2,3) CE(4,5) CE(6,7) CE(8,9) CE(10,11) CE(12,13) CE(14,15)
    CE(0,2) CE(1,3) CE(4,6) CE(5,7) CE(8,10) CE(9,11) CE(12,14) CE(13,15)
    CE(1,2) CE(5,6) CE(9,10) CE(13,14)
    CE(0,4) CE(1,5) CE(2,6) CE(3,7) CE(8,12) CE(9,13) CE(10,14) CE(11,15)
    CE(2,4) CE(3,5) CE(10,12) CE(11,13)
    CE(1,2) CE(3,4) CE(5,6) CE(9,10) CE(11,12) CE(13,14)
    CE(0,8) CE(1,9) CE(2,10) CE(3,11) CE(4,12) CE(5,13) CE(6,14) CE(7,15)
    CE(4,8) CE(5,9) CE(6,10) CE(7,11)
    CE(2,4) CE(3,5) CE(6,8) CE(7,9)
    CE(1,2) CE(3,4) CE(5,6) CE(7,8)

    // ---- branchless warp merge: kmin/imin are warp-uniform; lane r latches round r ----
    unsigned rk = 0xFFFFFFFFu, ri = 0;               // this lane's latched (key, idx)
    #pragma unroll
    for (int r = 0; r < KK; ++r) {
        unsigned mykey = (unsigned)(v[0] >> 9);
        unsigned kmin  = __reduce_min_sync(0xffffffffu, mykey);
        unsigned myidx = (unsigned)v[0] & 511u;
        unsigned cand  = (mykey == kmin) ? myidx : 1023u;
        unsigned imin  = __reduce_min_sync(0xffffffffu, cand);
        if (lane == r) { rk = kmin; ri = imin; }     // 2 SELs, no divergence cost
        bool pop = (mykey == kmin) && (myidx == imin);
        #pragma unroll
        for (int t = 0; t < 8; ++t) v[t] = pop ? v[t+1] : v[t];
        v[8] = pop ? ~0ull : v[8];
    }

    // ---- coalesced epilogue: lanes 0..8 write their round's result ----
    if (lane < KK) {
        const int seci = sSec[il];
        float d2v  = __uint_as_float(rk);
        bool  real = (d2v < REAL_THR_D2);
        float dv   = real ? sqrtf(d2v) : BIGF;
        bool  valid = real && (seci == sSec[ri]);
        size_t o0 = (size_t)ig * KK + lane;
        out[o0]                        = dv;
        out[(size_t)NTOT*KK     + o0]  = (float)ig;
        out[2*(size_t)NTOT*KK   + o0]  = valid ? (float)(gbase + (int)ri) : -1.0f;
        out[3*(size_t)NTOT*KK   + o0]  = valid ? 1.0f : 0.0f;
    }
}

extern "C" void kernel_launch(void* const* d_in, const int* in_sizes, int n_in,
                              void* d_out, int out_size)
{
    const float* X   = (const float*)d_in[0];
    const int*   AP  = (const int*)d_in[1];
    const int*   S   = (const int*)d_in[2];
    const int*   sec = (const int*)d_in[3];
    float* out = (float*)d_out;

    dist_kernel<<<BB * NPAIRS, 128>>>(X, AP, S);        // 1088 CTAs
    topk_kernel<<<BB * 64, 256>>>(sec, out);            // 512 CTAs
}